// round 14
// baseline (speedup 1.0000x reference)
#include <cuda_runtime.h>
#include <math.h>
#include <cstdint>

#define NT 256
#define HIDN 256
#define ENCLEN 16
#define DECLEN 25
#define NV 28

__device__ __forceinline__ float sigf(float x) {
    return __fdividef(1.0f, 1.0f + __expf(-x));
}
__device__ __forceinline__ float dot4(float4 a, float4 b) {
    return a.x * b.x + a.y * b.y + a.z * b.z + a.w * b.w;
}
__device__ __forceinline__ uint32_t smem_u32(const void* p) {
    return (uint32_t)__cvta_generic_to_shared(p);
}
__device__ __forceinline__ uint32_t mapa_rank(uint32_t laddr, int rk) {
    uint32_t ra;
    asm("mapa.shared::cluster.u32 %0, %1, %2;" : "=r"(ra) : "r"(laddr), "r"(rk));
    return ra;
}
__device__ __forceinline__ void st_async_f32(uint32_t ra_data, float v, uint32_t ra_mbar) {
    asm volatile(
        "st.async.weak.shared::cluster.mbarrier::complete_tx::bytes.b32 [%0], %1, [%2];"
        :: "r"(ra_data), "r"(__float_as_uint(v)), "r"(ra_mbar) : "memory");
}
__device__ __forceinline__ void mbar_init(uint32_t laddr, unsigned cnt) {
    asm volatile("mbarrier.init.shared.b64 [%0], %1;" :: "r"(laddr), "r"(cnt) : "memory");
}
__device__ __forceinline__ void mbar_expect(uint32_t laddr, unsigned bytes) {
    asm volatile("mbarrier.arrive.expect_tx.shared.b64 _, [%0], %1;"
                 :: "r"(laddr), "r"(bytes) : "memory");
}
__device__ __forceinline__ void mbar_wait(uint32_t laddr, unsigned parity) {
    unsigned done;
    asm volatile(
        "{\n\t.reg .pred p;\n\t"
        "mbarrier.try_wait.parity.acquire.cta.shared::cta.b64 p, [%1], %2;\n\t"
        "selp.b32 %0, 1, 0, p;\n\t}"
        : "=r"(done) : "r"(laddr), "r"(parity) : "memory");
    if (!done) {
        asm volatile(
            "{\n\t.reg .pred P1;\n\t"
            "WL_%=:\n\t"
            "mbarrier.try_wait.parity.acquire.cta.shared::cta.b64 P1, [%0], %1, 0x989680;\n\t"
            "@P1 bra.uni WD_%=;\n\t"
            "bra.uni WL_%=;\n\t"
            "WD_%=:\n\t}"
            :: "r"(laddr), "r"(parity) : "memory");
    }
}
__device__ __forceinline__ void cluster_sync_() {
    asm volatile("barrier.cluster.arrive.aligned;" ::: "memory");
    asm volatile("barrier.cluster.wait.aligned;" ::: "memory");
}

template<int CLS>
__global__ void __launch_bounds__(NT) vae_kernel(
    const int* __restrict__ data, const int* __restrict__ data_c, const int* __restrict__ target_c,
    const float* __restrict__ cond_emb, const float* __restrict__ enc_emb,
    const float* __restrict__ enc_Wih, const float* __restrict__ enc_Whh,
    const float* __restrict__ enc_bih, const float* __restrict__ enc_bhh,
    const float* __restrict__ hmu_W, const float* __restrict__ hmu_b,
    const float* __restrict__ cmu_W, const float* __restrict__ cmu_b,
    const float* __restrict__ fc1_W, const float* __restrict__ fc1_b,
    const float* __restrict__ fc2_W, const float* __restrict__ fc2_b,
    const float* __restrict__ dec_emb, const float* __restrict__ dec_Wih,
    const float* __restrict__ dec_Whh, const float* __restrict__ dec_bih,
    const float* __restrict__ dec_bhh, const float* __restrict__ out_W,
    const float* __restrict__ out_b,
    float* __restrict__ out, int out_size)
{
    constexpr int CELLS = HIDN / CLS;       // cells per CTA
    constexpr int ROWS  = 4 * CELLS;        // gate rows per CTA
    constexpr int TPR   = NT / ROWS;        // threads per row
    constexpr int NF4   = (HIDN / 4) / TPR; // float4 per thread chunk
    constexpr int RPW   = ROWS / 8;         // rows per warp
    constexpr int CPW   = RPW / 4;          // cells per warp

    extern __shared__ __align__(16) float xbuf[];       // 28KB staging
    __shared__ __align__(16) float hbuf[2][HIDN];
    __shared__ __align__(16) float cbuf[HIDN];
    __shared__ __align__(8) unsigned long long mbars[2];
    __shared__ float PE_s[ENCLEN * ROWS];
    __shared__ float PD_s[NV * ROWS];
    __shared__ float logits_s[32];
    __shared__ float outb_s[NV];
    __shared__ float mu_s[40], cmu_s[40];
    __shared__ int toks_s[ENCLEN];

    const int tid = threadIdx.x;
    const int crank = blockIdx.x;           // grid == cluster
    const int w = tid >> 5, l = tid & 31;
    const int rr = l / TPR;                 // row-in-warp
    const int qf = l % TPR;                 // k-chunk
    const int gate = rr / CPW, cj = rr % CPW;
    const int lr = w * RPW + rr;            // local row 0..ROWS-1
    const int G = gate * HIDN + CELLS * crank + CPW * w + cj;   // global gate row
    const bool prod = (rr < CPW) && (qf == 0);
    const int pcell_g = CELLS * crank + CPW * w + rr;  // valid when prod
    const int r3 = tid >> 3, q3 = tid & 7;
    const int r3c = (r3 < NV) ? r3 : 0;

    const uint32_t mb_l0 = smem_u32(&mbars[0]);
    const uint32_t mb_l1 = smem_u32(&mbars[1]);
    if (tid == 0) { mbar_init(mb_l0, 1); mbar_init(mb_l1, 1); }

    // ---- h0 = zeros(248) ++ cond_emb[data_c] ----
    {
        int dc = data_c[0];
        hbuf[0][tid] = (tid < HIDN - 8) ? 0.0f : cond_emb[dc * 8 + (tid - (HIDN - 8))];
        if (tid < ENCLEN) toks_s[tid] = data[tid];
        if (tid < NV) outb_s[tid] = out_b[tid];
    }
    __syncthreads();
    cluster_sync_();    // mbars initialized cluster-wide before any st.async

    // ---- xbuf := encoder embedding rows ----
    for (int idx = tid; idx < ENCLEN * (HIDN / 4); idx += NT) {
        int t = idx >> 6, c2 = idx & 63;
        ((float4*)xbuf)[idx] = ((const float4*)enc_emb)[toks_s[t] * 64 + c2];
    }
    __syncthreads();

    const float biasE = enc_bih[G] + enc_bhh[G];
    const float biasD = dec_bih[G] + dec_bhh[G];

    // ---- PE: enc_bias + enc_Wih @ x_t (wx4 temporarily holds enc_Wih) ----
    float4 wx4[NF4];
    {
        const float4* src = (const float4*)enc_Wih + (size_t)G * 64 + qf * NF4;
        #pragma unroll
        for (int k = 0; k < NF4; k++) wx4[k] = src[k];
        for (int t = 0; t < ENCLEN; t++) {
            const float4* xv = (const float4*)(xbuf + t * HIDN) + qf * NF4;
            float s0 = 0.f, s1 = 0.f;
            #pragma unroll
            for (int k = 0; k < NF4; k += 2) {
                s0 += dot4(wx4[k], xv[k]);
                s1 += dot4(wx4[k + 1], xv[k + 1]);
            }
            float acc = s0 + s1;
            #pragma unroll
            for (int o = 1; o < TPR; o <<= 1) acc += __shfl_xor_sync(~0u, acc, o);
            if (qf == 0) PE_s[t * ROWS + lr] = acc + biasE;
        }
    }
    __syncthreads();

    // ---- xbuf := relu(dec_emb); wx4 := dec_Wih (for interleaved PD) ----
    for (int idx = tid; idx < NV * (HIDN / 4); idx += NT) {
        float4 v = ((const float4*)dec_emb)[idx];
        v.x = fmaxf(v.x, 0.0f); v.y = fmaxf(v.y, 0.0f);
        v.z = fmaxf(v.z, 0.0f); v.w = fmaxf(v.w, 0.0f);
        ((float4*)xbuf)[idx] = v;
    }
    float4 w4[NF4];     // register Whh (encoder now, decoder later)
    {
        const float4* s1 = (const float4*)dec_Wih + (size_t)G * 64 + qf * NF4;
        const float4* s2 = (const float4*)enc_Whh + (size_t)G * 64 + qf * NF4;
        #pragma unroll
        for (int k = 0; k < NF4; k++) { wx4[k] = s1[k]; w4[k] = s2[k]; }
    }
    __syncthreads();

    // ---- producer DSMEM address bases (mapa once; derive by offset) ----
    uint32_t rkb[CLS];
    uint32_t dh0 = 0, dh1 = 0, dmb0 = 0, dmb1 = 0, dcc = 0;
    if (prod) {
        uint32_t base0 = smem_u32(&hbuf[0][0]);
        #pragma unroll
        for (int rk = 0; rk < CLS; rk++) rkb[rk] = mapa_rank(base0, rk);
        dh0 = smem_u32(&hbuf[0][pcell_g]) - base0;
        dh1 = smem_u32(&hbuf[1][pcell_g]) - base0;
        dmb0 = mb_l0 - base0;
        dmb1 = mb_l1 - base0;
        dcc = smem_u32(&cbuf[pcell_g]) - base0;
    }
    float c = prod ? hbuf[0][pcell_g] : 0.0f;
    int ph0 = 0, ph1 = 0;

    // step: compute gates from hbuf[(e-1)&1], publish h (and c) via st.async
    auto step_compute_publish = [&](const float* P, int e, bool emit_c) {
        const int ob = e & 1;
        if (tid == 0) mbar_expect(ob ? mb_l1 : mb_l0, emit_c ? 2048u : 1024u);
        const float4* hv = (const float4*)hbuf[ob ^ 1] + qf * NF4;
        float s0 = 0.f, s1 = 0.f;
        #pragma unroll
        for (int k = 0; k < NF4; k += 2) {
            s0 += dot4(w4[k], hv[k]);
            s1 += dot4(w4[k + 1], hv[k + 1]);
        }
        float acc = s0 + s1;
        #pragma unroll
        for (int o = 1; o < TPR; o <<= 1) acc += __shfl_xor_sync(~0u, acc, o);
        float val = acc + P[lr];
        float a = (gate == 2) ? tanhf(val) : sigf(val);
        float iv = __shfl_sync(~0u, a, (0 * CPW + cj) * TPR);
        float fv = __shfl_sync(~0u, a, (1 * CPW + cj) * TPR);
        float gv = __shfl_sync(~0u, a, (2 * CPW + cj) * TPR);
        float ov = __shfl_sync(~0u, a, (3 * CPW + cj) * TPR);
        if (prod) {
            float nc = fv * c + iv * gv;
            c = nc;
            float h = ov * tanhf(nc);
            uint32_t dh = ob ? dh1 : dh0;
            uint32_t dmb = ob ? dmb1 : dmb0;
            #pragma unroll
            for (int rk = 0; rk < CLS; rk++)
                st_async_f32(rkb[rk] + dh, h, rkb[rk] + dmb);
            if (emit_c) {
                #pragma unroll
                for (int rk = 0; rk < CLS; rk++)
                    st_async_f32(rkb[rk] + dcc, c, rkb[rk] + dmb);
            }
        }
    };
    auto step_wait = [&](int e) {
        if (e & 1) { mbar_wait(mb_l1, (unsigned)ph1); ph1 ^= 1; }
        else       { mbar_wait(mb_l0, (unsigned)ph0); ph0 ^= 1; }
    };

    // ================= encoder (e = 1..16), PD hidden in the bubbles =========
    for (int t = 0; t < ENCLEN; t++) {
        step_compute_publish(PE_s + t * ROWS, t + 1, t == ENCLEN - 1);
        int v0 = (t < 12) ? 2 * t : 24 + (t - 12);
        int nvv = (t < 12) ? 2 : 1;
        for (int j = 0; j < nvv; j++) {
            int v = v0 + j;
            const float4* xv = (const float4*)(xbuf + v * HIDN) + qf * NF4;
            float s0 = 0.f, s1 = 0.f;
            #pragma unroll
            for (int k = 0; k < NF4; k += 2) {
                s0 += dot4(wx4[k], xv[k]);
                s1 += dot4(wx4[k + 1], xv[k + 1]);
            }
            float acc = s0 + s1;
            #pragma unroll
            for (int o = 1; o < TPR; o <<= 1) acc += __shfl_xor_sync(~0u, acc, o);
            if (qf == 0) PD_s[v * ROWS + lr] = acc + biasD;
        }
        step_wait(t + 1);
    }

    // ================= latent transform (replicated per CTA) =================
    {
        float a1 = 0.0f, a2 = 0.0f;
        const float* whm = hmu_W + r3 * HIDN + q3 * 32;
        const float* wcm = cmu_W + r3 * HIDN + q3 * 32;
        #pragma unroll
        for (int k = 0; k < 32; k++) {
            a1 += whm[k] * hbuf[0][q3 * 32 + k];     // h16 (e=16 -> buffer 0)
            a2 += wcm[k] * cbuf[q3 * 32 + k];        // cT
        }
        a1 += __shfl_xor_sync(~0u, a1, 1); a1 += __shfl_xor_sync(~0u, a1, 2); a1 += __shfl_xor_sync(~0u, a1, 4);
        a2 += __shfl_xor_sync(~0u, a2, 1); a2 += __shfl_xor_sync(~0u, a2, 2); a2 += __shfl_xor_sync(~0u, a2, 4);
        if (q3 == 0) { mu_s[r3] = a1 + hmu_b[r3]; cmu_s[r3] = a2 + cmu_b[r3]; }
        if (tid < 8) {
            float tc = cond_emb[target_c[0] * 8 + tid];
            mu_s[32 + tid] = tc;
            cmu_s[32 + tid] = tc;
        }
        __syncthreads();   // PD interleave + hbuf0/cbuf reads all complete

        // xbuf := out_W for decoder logits (safe: PD done reading xbuf)
        for (int idx = tid; idx < NV * (HIDN / 4); idx += NT)
            ((float4*)xbuf)[idx] = ((const float4*)out_W)[idx];

        float d1 = fc1_b[tid], d2 = fc2_b[tid];
        const float* w1 = fc1_W + tid * 40;
        const float* w2 = fc2_W + tid * 40;
        #pragma unroll
        for (int k = 0; k < 40; k++) { d1 += w1[k] * mu_s[k]; d2 += w2[k] * cmu_s[k]; }
        __syncthreads();
        hbuf[0][tid] = d1;   // decoder h0 (identical in all CTAs; local write)
        cbuf[tid] = d2;      // decoder c0
        __syncthreads();
        if (prod) c = cbuf[pcell_g];
    }

    // ---- swap register weights to decoder Whh ----
    {
        const float4* s2 = (const float4*)dec_Whh + (size_t)G * 64 + qf * NF4;
        #pragma unroll
        for (int k = 0; k < NF4; k++) w4[k] = s2[k];
    }
    __syncthreads();

    // ================= decoder (e = 17..41), greedy =================
    int tok = 0;  // SOS
    for (int t = 0; t < DECLEN; t++) {
        int e = ENCLEN + 1 + t;
        step_compute_publish(PD_s + tok * ROWS, e, false);
        step_wait(e);
        const int ob = e & 1;

        float la = 0.0f;
        {
            const float4* wv = (const float4*)xbuf + r3c * 64 + q3 * 8;
            const float4* hv2 = (const float4*)hbuf[ob] + q3 * 8;
            #pragma unroll
            for (int k = 0; k < 8; k++) la += dot4(wv[k], hv2[k]);
        }
        la += __shfl_xor_sync(~0u, la, 1);
        la += __shfl_xor_sync(~0u, la, 2);
        la += __shfl_xor_sync(~0u, la, 4);
        if (q3 == 0 && r3 < NV) {
            float lg = la + outb_s[r3];
            logits_s[r3] = lg;
            if (crank == 0) out[t * NV + r3] = lg;
        }
        __syncthreads();
        // per-warp argmax (all warps read logits_s right after the barrier;
        // next write to logits_s is a full exchange round away)
        {
            float v = (l < NV) ? logits_s[l] : -1e30f;
            int idx = l;
            #pragma unroll
            for (int off = 1; off < 32; off <<= 1) {
                float ov2 = __shfl_xor_sync(~0u, v, off);
                int oi = __shfl_xor_sync(~0u, idx, off);
                if (ov2 > v || (ov2 == v && oi < idx)) { v = ov2; idx = oi; }
            }
            tok = idx;
            if (crank == 0 && tid == 0 && out_size >= DECLEN * NV + DECLEN)
                out[DECLEN * NV + t] = (float)idx;
        }
    }

    // no CTA exits while peers may still st.async into its smem
    cluster_sync_();
}

extern "C" void kernel_launch(void* const* d_in, const int* in_sizes, int n_in,
                              void* d_out, int out_size) {
    (void)in_sizes; (void)n_in;
    const size_t smem = (size_t)(NV * HIDN) * sizeof(float);   // 28KB

    cudaLaunchConfig_t cfg = {};
    cfg.blockDim = dim3(NT, 1, 1);
    cfg.dynamicSmemBytes = smem;
    cfg.stream = 0;
    cudaLaunchAttribute at[1];
    at[0].id = cudaLaunchAttributeClusterDimension;
    cfg.attrs = at;
    cfg.numAttrs = 1;

    // Prefer a 16-CTA cluster (nonportable size); fall back to 8.
    cudaFuncSetAttribute(vae_kernel<16>, cudaFuncAttributeMaxDynamicSharedMemorySize, (int)smem);
    cudaFuncSetAttribute(vae_kernel<16>, cudaFuncAttributeNonPortableClusterSizeAllowed, 1);
    cfg.gridDim = dim3(16, 1, 1);
    at[0].val.clusterDim = {16, 1, 1};
    int ncl = 0;
    cudaError_t qe = cudaOccupancyMaxActiveClusters(&ncl, vae_kernel<16>, &cfg);
    bool use16 = (qe == cudaSuccess && ncl >= 1);
    if (!use16) (void)cudaGetLastError();   // clear sticky error from the query

    if (use16) {
        cudaLaunchKernelEx(&cfg, vae_kernel<16>,
            (const int*)d_in[0], (const int*)d_in[1], (const int*)d_in[2],
            (const float*)d_in[3], (const float*)d_in[4],
            (const float*)d_in[5], (const float*)d_in[6],
            (const float*)d_in[7], (const float*)d_in[8],
            (const float*)d_in[9], (const float*)d_in[10],
            (const float*)d_in[11], (const float*)d_in[12],
            (const float*)d_in[13], (const float*)d_in[14],
            (const float*)d_in[15], (const float*)d_in[16],
            (const float*)d_in[17], (const float*)d_in[18],
            (const float*)d_in[19], (const float*)d_in[20],
            (const float*)d_in[21], (const float*)d_in[22],
            (const float*)d_in[23],
            (float*)d_out, out_size);
    } else {
        cudaFuncSetAttribute(vae_kernel<8>, cudaFuncAttributeMaxDynamicSharedMemorySize, (int)smem);
        cfg.gridDim = dim3(8, 1, 1);
        at[0].val.clusterDim = {8, 1, 1};
        cudaLaunchKernelEx(&cfg, vae_kernel<8>,
            (const int*)d_in[0], (const int*)d_in[1], (const int*)d_in[2],
            (const float*)d_in[3], (const float*)d_in[4],
            (const float*)d_in[5], (const float*)d_in[6],
            (const float*)d_in[7], (const float*)d_in[8],
            (const float*)d_in[9], (const float*)d_in[10],
            (const float*)d_in[11], (const float*)d_in[12],
            (const float*)d_in[13], (const float*)d_in[14],
            (const float*)d_in[15], (const float*)d_in[16],
            (const float*)d_in[17], (const float*)d_in[18],
            (const float*)d_in[19], (const float*)d_in[20],
            (const float*)d_in[21], (const float*)d_in[22],
            (const float*)d_in[23],
            (float*)d_out, out_size);
    }
}